// round 7
// baseline (speedup 1.0000x reference)
#include <cuda_runtime.h>
#include <math.h>

#define B_ROWS   2048
#define NL       64
#define NN       16
#define NO       2048
#define ZSTRIDE  80          // NL + NN
#define TILE_B   32          // rows per tile (fine-grain, low ragged waste)
#define CHUNK_O  128         // cols per task
#define N_OCHUNK (NO / CHUNK_O)    // 16
#define MAX_TILES 80         // <= B/TILE_B + NN
#define NTHREADS 256
#define GEMM_GRID 444        // 3 blocks per SM (148 SMs)

// ---------------- device scratch (no allocations allowed) ----------------
__device__ int   g_nid[B_ROWS];
__device__ int   g_order[B_ROWS];
__device__ int   g_bucket_base[NN + 1];
__device__ int   g_tile_bucket[MAX_TILES];
__device__ int   g_tile_start[MAX_TILES];
__device__ int   g_tile_cnt[MAX_TILES];
__device__ int   g_num_tasks;
__device__ int   g_task_ctr;
__device__ float g_logits[(size_t)B_ROWS * NO];   // 16 MB scratch (L2-resident)

// ---------------- kernel 1: per-row argmax of nuisance one-hot + theta ----
__global__ void k_prep(const float* __restrict__ z,
                       const float* __restrict__ px_r,
                       float* __restrict__ theta_out)
{
    int g = blockIdx.x * blockDim.x + threadIdx.x;
    if (g < B_ROWS) {
        const float* p = z + (size_t)g * ZSTRIDE + NL;
        float best = p[0]; int bi = 0;
        #pragma unroll
        for (int i = 1; i < NN; i++) {
            float v = p[i];
            if (v > best) { best = v; bi = i; }   // first-max wins (jnp.argmax)
        }
        g_nid[g] = bi;
    }
    if (g < NO) theta_out[g] = expf(px_r[g]);
}

// ---------------- kernel 2: counting sort by nid + tile/task list ---------
__global__ void k_sort()
{
    __shared__ int cnt[NN];
    __shared__ int offs[NN];
    int t = threadIdx.x;
    if (t < NN) cnt[t] = 0;
    __syncthreads();
    for (int b = t; b < B_ROWS; b += blockDim.x)
        atomicAdd(&cnt[g_nid[b]], 1);
    __syncthreads();
    if (t == 0) {
        int acc = 0;
        for (int i = 0; i < NN; i++) {
            g_bucket_base[i] = acc;
            offs[i] = acc;
            acc += cnt[i];
        }
        g_bucket_base[NN] = acc;
    }
    __syncthreads();
    for (int b = t; b < B_ROWS; b += blockDim.x) {
        int p = atomicAdd(&offs[g_nid[b]], 1);
        g_order[p] = b;
    }
    if (t == 0) {
        int nt = 0;
        for (int i = 0; i < NN; i++) {
            int base = g_bucket_base[i];
            int c    = g_bucket_base[i + 1] - base;
            for (int s = 0; s < c; s += TILE_B) {
                g_tile_bucket[nt] = i;
                g_tile_start[nt]  = base + s;
                g_tile_cnt[nt]    = min(TILE_B, c - s);
                nt++;
            }
        }
        g_num_tasks = nt * N_OCHUNK;
        g_task_ctr  = 0;              // reset work queue every launch/replay
    }
}

// Z tile swizzle: [r][64] row-major; float4-group column c4 (0..15) XORed by
// (r & 3) so the 4 consecutive rows held by one warp hit distinct banks.
__device__ __forceinline__ int zc4(int r, int c4)
{
    return c4 ^ (r & 3);
}

// ---------------- kernel 3: persistent bucketed GEMM ----------------------
// task = (tile, ochunk): 32 rows x 128 cols, K=64 full.
// logits = Z0 @ (W + S[bucket]) + offsets[bucket]
__global__ __launch_bounds__(NTHREADS)
void k_gemm(const float* __restrict__ z,
            const float* __restrict__ W,
            const float* __restrict__ S,
            const float* __restrict__ offsets)
{
    __shared__ float Zs[TILE_B * NL];      // 8 KB
    __shared__ float As[NL * CHUNK_O];     // 32 KB
    __shared__ int   s_task;

    int tid = threadIdx.x;
    int tx  = tid & 15;    // col group: cols {tx*4..+3} and {64+tx*4..+3}
    int ty  = tid >> 4;    // row group: rows ty*2, ty*2+1

    const float4* W4 = (const float4*)W;
    int n_tasks = g_num_tasks;

    for (;;) {
        if (tid == 0) s_task = atomicAdd(&g_task_ctr, 1);
        __syncthreads();               // publish s_task; guard smem reuse
        int task = s_task;
        if (task >= n_tasks) return;

        int tile   = task >> 4;        // N_OCHUNK == 16
        int oc     = task & 15;
        int bucket = g_tile_bucket[tile];
        int start  = g_tile_start[tile];
        int vcnt   = g_tile_cnt[tile];
        int o0     = oc * CHUNK_O;

        const float4* S4 = (const float4*)(S + (size_t)bucket * NL * NO);

        // ---- stage Z (32 rows x 16 float4 = 512 float4) ----
        #pragma unroll
        for (int j = 0; j < 2; j++) {
            int e  = tid + j * NTHREADS;    // 0..511
            int r  = e >> 4;
            int l4 = e & 15;
            int row = (r < vcnt) ? g_order[start + r] : -1;
            float4 v = make_float4(0.f, 0.f, 0.f, 0.f);
            if (row >= 0)
                v = *(const float4*)(z + (size_t)row * ZSTRIDE + l4 * 4);
            *(float4*)(Zs + r * NL + zc4(r, l4) * 4) = v;
        }
        // ---- stage A_eff = W + S[bucket] (64 x 128 floats = 2048 float4) --
        {
            int ob4 = o0 >> 2;
            #pragma unroll
            for (int j = 0; j < 8; j++) {
                int e  = tid + j * NTHREADS;    // 0..2047
                int k  = e >> 5;
                int c4 = e & 31;
                float4 w = W4[(size_t)k * (NO / 4) + ob4 + c4];
                float4 s = S4[(size_t)k * (NO / 4) + ob4 + c4];
                ((float4*)(As + k * CHUNK_O))[c4] =
                    make_float4(w.x + s.x, w.y + s.y, w.z + s.z, w.w + s.w);
            }
        }
        __syncthreads();

        float acc[2][8];
        #pragma unroll
        for (int i = 0; i < 2; i++)
            #pragma unroll
            for (int j = 0; j < 8; j++) acc[i][j] = 0.f;

        #pragma unroll 4
        for (int k4 = 0; k4 < NL; k4 += 4) {
            float4 zq[2];
            #pragma unroll
            for (int i = 0; i < 2; i++) {
                int r = ty * 2 + i;
                zq[i] = *(const float4*)(Zs + r * NL + zc4(r, k4 >> 2) * 4);
            }
            #pragma unroll
            for (int kk = 0; kk < 4; kk++) {
                float4 a0 = *(const float4*)(As + (k4 + kk) * CHUNK_O + tx * 4);
                float4 a1 = *(const float4*)(As + (k4 + kk) * CHUNK_O + 64 + tx * 4);
                #pragma unroll
                for (int i = 0; i < 2; i++) {
                    float zv = (&zq[i].x)[kk];
                    acc[i][0] += zv * a0.x;
                    acc[i][1] += zv * a0.y;
                    acc[i][2] += zv * a0.z;
                    acc[i][3] += zv * a0.w;
                    acc[i][4] += zv * a1.x;
                    acc[i][5] += zv * a1.y;
                    acc[i][6] += zv * a1.z;
                    acc[i][7] += zv * a1.w;
                }
            }
        }

        // ---- epilogue: + offsets[bucket], scatter rows to logits scratch --
        const float4 offlo = *(const float4*)(offsets + (size_t)bucket * NO + o0 + tx * 4);
        const float4 offhi = *(const float4*)(offsets + (size_t)bucket * NO + o0 + 64 + tx * 4);
        #pragma unroll
        for (int i = 0; i < 2; i++) {
            int r = ty * 2 + i;
            if (r >= vcnt) continue;
            int row = g_order[start + r];
            float* dst = g_logits + (size_t)row * NO + o0;
            *(float4*)(dst + tx * 4) =
                make_float4(acc[i][0] + offlo.x, acc[i][1] + offlo.y,
                            acc[i][2] + offlo.z, acc[i][3] + offlo.w);
            *(float4*)(dst + 64 + tx * 4) =
                make_float4(acc[i][4] + offhi.x, acc[i][5] + offhi.y,
                            acc[i][6] + offhi.z, acc[i][7] + offhi.w);
        }
    }
}

// ---------------- kernel 4: row softmax * size_factor ---------------------
// One warp per row, no smem, no barriers. 32 lanes x 16 float4 = 2048 cols.
__global__ __launch_bounds__(NTHREADS)
void k_softmax(const float* __restrict__ sf, float* __restrict__ mu)
{
    int lane = threadIdx.x & 31;
    int wid  = threadIdx.x >> 5;
    int b    = blockIdx.x * 8 + wid;

    const float4* src = (const float4*)g_logits + (size_t)b * (NO / 4);
    float4 v[16];
    #pragma unroll
    for (int q = 0; q < 16; q++) v[q] = src[lane + q * 32];

    float mx = -1e30f;
    #pragma unroll
    for (int q = 0; q < 16; q++)
        mx = fmaxf(mx, fmaxf(fmaxf(v[q].x, v[q].y), fmaxf(v[q].z, v[q].w)));
    #pragma unroll
    for (int o = 16; o; o >>= 1)
        mx = fmaxf(mx, __shfl_xor_sync(0xffffffffu, mx, o));

    float s = 0.f;
    #pragma unroll
    for (int q = 0; q < 16; q++) {
        v[q].x = __expf(v[q].x - mx);
        v[q].y = __expf(v[q].y - mx);
        v[q].z = __expf(v[q].z - mx);
        v[q].w = __expf(v[q].w - mx);
        s += (v[q].x + v[q].y) + (v[q].z + v[q].w);
    }
    #pragma unroll
    for (int o = 16; o; o >>= 1)
        s += __shfl_xor_sync(0xffffffffu, s, o);

    float scale = sf[b] / s;
    float4* dst = (float4*)mu + (size_t)b * (NO / 4);
    #pragma unroll
    for (int q = 0; q < 16; q++)
        dst[lane + q * 32] = make_float4(v[q].x * scale, v[q].y * scale,
                                         v[q].z * scale, v[q].w * scale);
}

// -------------------------------------------------------------------------
extern "C" void kernel_launch(void* const* d_in, const int* in_sizes, int n_in,
                              void* d_out, int out_size)
{
    const float* z       = (const float*)d_in[0];
    const float* sf      = (const float*)d_in[1];
    const float* W       = (const float*)d_in[2];
    const float* S       = (const float*)d_in[3];
    const float* offsets = (const float*)d_in[4];
    const float* px_r    = (const float*)d_in[5];
    float* out   = (float*)d_out;
    float* theta = out + (out_size - NO);   // layout: mu[B,NO] then theta[NO]

    k_prep<<<(B_ROWS + NTHREADS - 1) / NTHREADS, NTHREADS>>>(z, px_r, theta);
    k_sort<<<1, NTHREADS>>>();
    k_gemm<<<GEMM_GRID, NTHREADS>>>(z, W, S, offsets);
    k_softmax<<<B_ROWS / 8, NTHREADS>>>(sf, out);
}

// round 8
// speedup vs baseline: 1.3801x; 1.3801x over previous
#include <cuda_runtime.h>
#include <math.h>

#define B_ROWS   2048
#define NL       64
#define NN       16
#define NO       2048
#define ZSTRIDE  80          // NL + NN
#define TILE_B   64
#define CHUNK_O  128         // A-chunk staged in smem
#define TILE_O   256         // per-block o coverage (2 chunks)
#define MAX_TILES 48
#define NTHREADS 256

// ---------------- device scratch (no allocations allowed) ----------------
__device__ int   g_nid[B_ROWS];
__device__ int   g_order[B_ROWS];
__device__ int   g_bucket_base[NN + 1];
__device__ int   g_tile_bucket[MAX_TILES];
__device__ int   g_tile_start[MAX_TILES];
__device__ int   g_tile_cnt[MAX_TILES];
__device__ int   g_num_tiles;
__device__ float g_logits[(size_t)B_ROWS * NO];   // 16 MB scratch (L2-resident)

// ---------------- packed f32x2 helpers (sm_103a FFMA2 via PTX) ------------
__device__ __forceinline__ void ffma2(unsigned long long& acc,
                                      unsigned long long a,
                                      unsigned long long b)
{
    asm("fma.rn.f32x2 %0, %1, %2, %0;" : "+l"(acc) : "l"(a), "l"(b));
}
__device__ __forceinline__ unsigned long long bcast2(float v)
{
    unsigned long long r;
    asm("mov.b64 %0, {%1, %1};" : "=l"(r) : "f"(v));
    return r;
}
__device__ __forceinline__ float2 unpack2(unsigned long long p)
{
    float2 f;
    asm("mov.b64 {%0, %1}, %2;" : "=f"(f.x), "=f"(f.y) : "l"(p));
    return f;
}

// ---------------- kernel 1: per-row argmax of nuisance one-hot + theta ----
__global__ void k_prep(const float* __restrict__ z,
                       const float* __restrict__ px_r,
                       float* __restrict__ theta_out)
{
    int g = blockIdx.x * blockDim.x + threadIdx.x;
    if (g < B_ROWS) {
        const float* p = z + (size_t)g * ZSTRIDE + NL;
        float best = p[0]; int bi = 0;
        #pragma unroll
        for (int i = 1; i < NN; i++) {
            float v = p[i];
            if (v > best) { best = v; bi = i; }   // first-max wins (jnp.argmax)
        }
        g_nid[g] = bi;
    }
    if (g < NO) theta_out[g] = expf(px_r[g]);
}

// ---------------- kernel 2: counting sort by nid + tile list --------------
__global__ void k_sort()
{
    __shared__ int cnt[NN];
    __shared__ int offs[NN];
    int t = threadIdx.x;
    if (t < NN) cnt[t] = 0;
    __syncthreads();
    for (int b = t; b < B_ROWS; b += blockDim.x)
        atomicAdd(&cnt[g_nid[b]], 1);
    __syncthreads();
    if (t == 0) {
        int acc = 0;
        for (int i = 0; i < NN; i++) {
            g_bucket_base[i] = acc;
            offs[i] = acc;
            acc += cnt[i];
        }
        g_bucket_base[NN] = acc;
    }
    __syncthreads();
    for (int b = t; b < B_ROWS; b += blockDim.x) {
        int p = atomicAdd(&offs[g_nid[b]], 1);
        g_order[p] = b;
    }
    if (t == 0) {
        int nt = 0;
        for (int i = 0; i < NN; i++) {
            int base = g_bucket_base[i];
            int c    = g_bucket_base[i + 1] - base;
            for (int s = 0; s < c; s += TILE_B) {
                g_tile_bucket[nt] = i;
                g_tile_start[nt]  = base + s;
                g_tile_cnt[nt]    = min(TILE_B, c - s);
                nt++;
            }
        }
        g_num_tiles = nt;
    }
}

// Z tile swizzle: row-major [r][64], float4-group column c4 (0..15) XORed by
// a bit derived from r so that rows r and r+4 (the two ty-groups of a warp)
// land 16 banks apart. Mainloop loads are LDS.128, conflict-free.
__device__ __forceinline__ int zc4(int r, int c4)
{
    return c4 ^ (((r >> 2) & 1) << 2);
}

// ---------------- kernel 3: bucketed GEMM  logits = Z0 @ (W + S[nid]) + off
// Dynamic smem = 64*64 (Zs) + 64*128 (As) floats = 49152 B exactly.
// Inner loop uses packed fma.rn.f32x2 (FFMA2): ulonglong2 LDS.128 of As gives
// two (col,col+1) f32x2 operands for free; z is broadcast-packed per row.
__global__ __launch_bounds__(NTHREADS)
void k_gemm(const float* __restrict__ z,
            const float* __restrict__ W,
            const float* __restrict__ S,
            const float* __restrict__ offsets)
{
    int tile = blockIdx.x;
    if (tile >= g_num_tiles) return;

    extern __shared__ float sm[];
    float* Zs = sm;                       // [64][64] row-major, swizzled c4
    float* As = sm + TILE_B * NL;         // [64][128]

    int tid    = threadIdx.x;
    int bucket = g_tile_bucket[tile];
    int start  = g_tile_start[tile];
    int vcnt   = g_tile_cnt[tile];

    int tx = tid & 15;     // col group: cols {tx*4..+3} and {64+tx*4..+3}
    int ty = tid >> 4;     // row group: rows ty*4..+3

    // row indices for this thread's 4 output rows (register-cached)
    int rowidx[4];
    #pragma unroll
    for (int i = 0; i < 4; i++) {
        int r = ty * 4 + i;
        rowidx[i] = (r < vcnt) ? g_order[start + r] : -1;
    }

    // ---- stage Z row-major swizzled (64 rows x 16 float4 = 1024 float4) ----
    {
        #pragma unroll
        for (int j = 0; j < 4; j++) {
            int e  = tid + j * NTHREADS;   // 0..1023
            int r  = e >> 4;
            int l4 = e & 15;
            int row = (r < vcnt) ? g_order[start + r] : -1;
            float4 v = make_float4(0.f, 0.f, 0.f, 0.f);
            if (row >= 0)
                v = *(const float4*)(z + (size_t)row * ZSTRIDE + l4 * 4);
            *(float4*)(Zs + r * NL + zc4(r, l4) * 4) = v;
        }
    }

    const float4* W4 = (const float4*)W;
    const float4* S4 = (const float4*)(S + (size_t)bucket * NL * NO);

    #pragma unroll
    for (int chunk = 0; chunk < TILE_O / CHUNK_O; chunk++) {
        int o0 = blockIdx.y * TILE_O + chunk * CHUNK_O;

        __syncthreads();   // Z stage done (chunk 0) / prior compute reads done

        // ---- stage A_eff = W + S[bucket] (64 x 128 floats = 2048 float4) --
        {
            int ob4 = o0 >> 2;
            #pragma unroll
            for (int j = 0; j < 8; j++) {
                int e  = tid + j * NTHREADS;   // 0..2047
                int k  = e >> 5;
                int c4 = e & 31;
                float4 w = W4[(size_t)k * (NO / 4) + ob4 + c4];
                float4 s = S4[(size_t)k * (NO / 4) + ob4 + c4];
                ((float4*)(As + k * CHUNK_O))[c4] =
                    make_float4(w.x + s.x, w.y + s.y, w.z + s.z, w.w + s.w);
            }
        }
        __syncthreads();

        // packed accumulators: acc[i][j] = (col 2j, col 2j+1) of group
        unsigned long long acc[4][8];
        #pragma unroll
        for (int i = 0; i < 4; i++)
            #pragma unroll
            for (int j = 0; j < 8; j++) acc[i][j] = 0ull;

        #pragma unroll 4
        for (int k4 = 0; k4 < NL; k4 += 4) {
            float4 zq[4];
            #pragma unroll
            for (int i = 0; i < 4; i++) {
                int r = ty * 4 + i;
                zq[i] = *(const float4*)(Zs + r * NL + zc4(r, k4 >> 2) * 4);
            }
            #pragma unroll
            for (int kk = 0; kk < 4; kk++) {
                ulonglong2 a0 = *(const ulonglong2*)(As + (k4 + kk) * CHUNK_O + tx * 4);
                ulonglong2 a1 = *(const ulonglong2*)(As + (k4 + kk) * CHUNK_O + 64 + tx * 4);
                #pragma unroll
                for (int i = 0; i < 4; i++) {
                    unsigned long long zz = bcast2((&zq[i].x)[kk]);
                    ffma2(acc[i][0], zz, a0.x);
                    ffma2(acc[i][1], zz, a0.y);
                    ffma2(acc[i][2], zz, a1.x);
                    ffma2(acc[i][3], zz, a1.y);
                }
            }
        }

        // ---- epilogue: + offsets[bucket], scatter rows to logits scratch --
        const float4 offlo = *(const float4*)(offsets + (size_t)bucket * NO + o0 + tx * 4);
        const float4 offhi = *(const float4*)(offsets + (size_t)bucket * NO + o0 + 64 + tx * 4);
        #pragma unroll
        for (int i = 0; i < 4; i++) {
            int row = rowidx[i];
            if (row < 0) continue;
            float2 p0 = unpack2(acc[i][0]);
            float2 p1 = unpack2(acc[i][1]);
            float2 p2 = unpack2(acc[i][2]);
            float2 p3 = unpack2(acc[i][3]);
            float* dst = g_logits + (size_t)row * NO + o0;
            *(float4*)(dst + tx * 4) =
                make_float4(p0.x + offlo.x, p0.y + offlo.y,
                            p1.x + offlo.z, p1.y + offlo.w);
            *(float4*)(dst + 64 + tx * 4) =
                make_float4(p2.x + offhi.x, p2.y + offhi.y,
                            p3.x + offhi.z, p3.y + offhi.w);
        }
    }
}

// ---------------- kernel 4: row softmax * size_factor (flash, 2 rows/block)
// 128 threads per row; each thread covers 4 float4 = 16 of 2048 elements.
__global__ __launch_bounds__(NTHREADS)
void k_softmax(const float* __restrict__ sf, float* __restrict__ mu)
{
    int tid  = threadIdx.x;
    int half = tid >> 7;                 // 0/1: which row of this block
    int t    = tid & 127;                // position within row (float4 units)
    int b    = blockIdx.x * 2 + half;
    int lane = tid & 31;
    int wid  = tid >> 5;                 // 0..7 (warps 0-3 row0, 4-7 row1)

    const float4* src = (const float4*)g_logits + (size_t)b * (NO / 4);
    float4 v[4];
    #pragma unroll
    for (int q = 0; q < 4; q++) v[q] = src[t + q * 128];

    // per-warp max over this thread's 16 values
    float mx = -1e30f;
    #pragma unroll
    for (int q = 0; q < 4; q++)
        mx = fmaxf(mx, fmaxf(fmaxf(v[q].x, v[q].y), fmaxf(v[q].z, v[q].w)));
    #pragma unroll
    for (int o = 16; o; o >>= 1)
        mx = fmaxf(mx, __shfl_xor_sync(0xffffffffu, mx, o));

    // per-warp sum of exp(v - warp_max)
    float e[16];
    float s = 0.f;
    #pragma unroll
    for (int q = 0; q < 4; q++) {
        e[q * 4 + 0] = __expf(v[q].x - mx);
        e[q * 4 + 1] = __expf(v[q].y - mx);
        e[q * 4 + 2] = __expf(v[q].z - mx);
        e[q * 4 + 3] = __expf(v[q].w - mx);
        s += (e[q * 4 + 0] + e[q * 4 + 1]) + (e[q * 4 + 2] + e[q * 4 + 3]);
    }
    #pragma unroll
    for (int o = 16; o; o >>= 1)
        s += __shfl_xor_sync(0xffffffffu, s, o);

    __shared__ float smax[8];
    __shared__ float ssum[8];
    if (lane == 0) { smax[wid] = mx; ssum[wid] = s; }
    __syncthreads();

    int w0 = half * 4;   // this row's warps: w0..w0+3
    float M = fmaxf(fmaxf(smax[w0], smax[w0 + 1]),
                    fmaxf(smax[w0 + 2], smax[w0 + 3]));
    float Ssum = ssum[w0]     * __expf(smax[w0]     - M)
               + ssum[w0 + 1] * __expf(smax[w0 + 1] - M)
               + ssum[w0 + 2] * __expf(smax[w0 + 2] - M)
               + ssum[w0 + 3] * __expf(smax[w0 + 3] - M);

    // rescale warp-local exps: e * exp(mx - M) / Ssum * sf
    float scale = (sf[b] / Ssum) * __expf(mx - M);

    float4* dst = (float4*)mu + (size_t)b * (NO / 4);
    #pragma unroll
    for (int q = 0; q < 4; q++)
        dst[t + q * 128] = make_float4(e[q * 4 + 0] * scale, e[q * 4 + 1] * scale,
                                       e[q * 4 + 2] * scale, e[q * 4 + 3] * scale);
}

// -------------------------------------------------------------------------
extern "C" void kernel_launch(void* const* d_in, const int* in_sizes, int n_in,
                              void* d_out, int out_size)
{
    const float* z       = (const float*)d_in[0];
    const float* sf      = (const float*)d_in[1];
    const float* W       = (const float*)d_in[2];
    const float* S       = (const float*)d_in[3];
    const float* offsets = (const float*)d_in[4];
    const float* px_r    = (const float*)d_in[5];
    float* out   = (float*)d_out;
    float* theta = out + (out_size - NO);   // layout: mu[B,NO] then theta[NO]

    k_prep<<<(B_ROWS + NTHREADS - 1) / NTHREADS, NTHREADS>>>(z, px_r, theta);
    k_sort<<<1, NTHREADS>>>();

    size_t smem = (size_t)(TILE_B * NL + NL * CHUNK_O) * sizeof(float);  // 49152 B
    k_gemm<<<dim3(MAX_TILES, NO / TILE_O), NTHREADS, smem>>>(z, W, S, offsets);

    k_softmax<<<B_ROWS / 2, NTHREADS>>>(sf, out);
}